// round 7
// baseline (speedup 1.0000x reference)
#include <cuda_runtime.h>
#include <cstdint>

// KL(p||q) diag-Gaussian, mean over batch — async-bulk-copy pipeline version.
// cp.async.bulk (async proxy DMA) -> smem double buffer -> compute from smem.
// 592 CTAs x 256 thr, tile = 1024 floats/array, 2 stages (32KB static smem).
// Deterministic: fixed tile order per CTA, fixed-order last-block reduction.

#define NTHREADS 256
#define GRID 592
#define TILE_FLOATS 1024
#define TILE_BYTES (TILE_FLOATS * 4)
#define STAGES 2

__device__ float g_partials[GRID];
__device__ unsigned int g_ticket = 0;

static __device__ __forceinline__ uint32_t smem_u32(const void* p) {
    uint32_t a;
    asm("{ .reg .u64 t; cvta.to.shared.u64 t, %1; cvt.u32.u64 %0, t; }"
        : "=r"(a) : "l"(p));
    return a;
}
static __device__ __forceinline__ void mbar_init(uint32_t m, uint32_t cnt) {
    asm volatile("mbarrier.init.shared.b64 [%0], %1;" :: "r"(m), "r"(cnt) : "memory");
}
static __device__ __forceinline__ void mbar_arrive(uint32_t m) {
    asm volatile("mbarrier.arrive.shared.b64 _, [%0];" :: "r"(m) : "memory");
}
static __device__ __forceinline__ void mbar_expect_tx(uint32_t m, uint32_t bytes) {
    asm volatile("mbarrier.arrive.expect_tx.shared.b64 _, [%0], %1;"
                 :: "r"(m), "r"(bytes) : "memory");
}
static __device__ __forceinline__ void mbar_wait(uint32_t m, uint32_t parity) {
    asm volatile(
        "{\n\t.reg .pred P;\n"
        "WAIT_%=:\n\t"
        "mbarrier.try_wait.parity.acquire.cta.shared::cta.b64 P, [%0], %1, 0x989680;\n\t"
        "@P bra.uni DONE_%=;\n\t"
        "bra.uni WAIT_%=;\n"
        "DONE_%=:\n\t}"
        :: "r"(m), "r"(parity) : "memory");
}
static __device__ __forceinline__ void mbar_wait_relaxed(uint32_t m, uint32_t parity) {
    asm volatile(
        "{\n\t.reg .pred P;\n"
        "WAITR_%=:\n\t"
        "mbarrier.try_wait.parity.relaxed.cta.shared::cta.b64 P, [%0], %1, 0x989680;\n\t"
        "@P bra.uni DONER_%=;\n\t"
        "bra.uni WAITR_%=;\n"
        "DONER_%=:\n\t}"
        :: "r"(m), "r"(parity) : "memory");
}
static __device__ __forceinline__ void bulk_g2s(uint32_t dst, const void* src,
                                                uint32_t bytes, uint32_t mbar) {
    asm volatile(
        "cp.async.bulk.shared::cta.global.mbarrier::complete_tx::bytes [%0], [%1], %2, [%3];"
        :: "r"(dst), "l"(src), "r"(bytes), "r"(mbar) : "memory");
}

__device__ __forceinline__ float kl_term(float pm, float pl, float qm, float ql)
{
    float lr = ql - pl;
    float dm = pm - qm;
    return lr + __expf(-lr) + dm * dm * __expf(-ql) - 1.0f;
}

__global__ __launch_bounds__(NTHREADS) void kl_bulk_kernel(
    const float* __restrict__ p_mu,
    const float* __restrict__ p_lv,
    const float* __restrict__ q_mu,
    const float* __restrict__ q_lv,
    float* __restrict__ out,
    int n_tiles, float scale)
{
    __shared__ __align__(128) float s_buf[STAGES][4][TILE_FLOATS];   // 32 KB
    __shared__ __align__(8) unsigned long long s_full[STAGES];
    __shared__ __align__(8) unsigned long long s_empty[STAGES];

    const int tid = threadIdx.x;

    uint32_t full_a[STAGES], empty_a[STAGES], buf_a[STAGES][4];
    #pragma unroll
    for (int s = 0; s < STAGES; ++s) {
        full_a[s]  = smem_u32(&s_full[s]);
        empty_a[s] = smem_u32(&s_empty[s]);
        #pragma unroll
        for (int r = 0; r < 4; ++r)
            buf_a[s][r] = smem_u32(&s_buf[s][r][0]);
    }

    if (tid == 0) {
        #pragma unroll
        for (int s = 0; s < STAGES; ++s) {
            mbar_init(full_a[s], 1);          // producer's expect_tx arrival
            mbar_init(empty_a[s], NTHREADS);  // all consumers arrive
        }
    }
    __syncthreads();
    // Prime: complete phase 0 of both empty barriers so first producer wait passes.
    #pragma unroll
    for (int s = 0; s < STAGES; ++s)
        mbar_arrive(empty_a[s]);

    float acc = 0.0f;
    int stage = 0, phase = 0;

    for (int t = blockIdx.x; t < n_tiles; t += GRID) {
        const long off = (long)t * TILE_FLOATS;

        if (tid == 0) {
            mbar_wait_relaxed(empty_a[stage], phase);
            mbar_expect_tx(full_a[stage], 4 * TILE_BYTES);
            bulk_g2s(buf_a[stage][0], p_mu + off, TILE_BYTES, full_a[stage]);
            bulk_g2s(buf_a[stage][1], p_lv + off, TILE_BYTES, full_a[stage]);
            bulk_g2s(buf_a[stage][2], q_mu + off, TILE_BYTES, full_a[stage]);
            bulk_g2s(buf_a[stage][3], q_lv + off, TILE_BYTES, full_a[stage]);
        }

        mbar_wait(full_a[stage], phase);

        const int j = tid * 4;
        float4 a = *reinterpret_cast<const float4*>(&s_buf[stage][0][j]);
        float4 b = *reinterpret_cast<const float4*>(&s_buf[stage][1][j]);
        float4 c = *reinterpret_cast<const float4*>(&s_buf[stage][2][j]);
        float4 d = *reinterpret_cast<const float4*>(&s_buf[stage][3][j]);

        acc += kl_term(a.x, b.x, c.x, d.x);
        acc += kl_term(a.y, b.y, c.y, d.y);
        acc += kl_term(a.z, b.z, c.z, d.z);
        acc += kl_term(a.w, b.w, c.w, d.w);

        mbar_arrive(empty_a[stage]);

        if (++stage == STAGES) { stage = 0; phase ^= 1; }
    }

    // Block reduce
    #pragma unroll
    for (int off = 16; off > 0; off >>= 1)
        acc += __shfl_down_sync(0xFFFFFFFFu, acc, off);

    __shared__ float s_red[NTHREADS / 32];
    __shared__ bool s_is_last;
    const int lane = tid & 31;
    const int warp = tid >> 5;
    if (lane == 0) s_red[warp] = acc;
    __syncthreads();

    if (warp == 0) {
        acc = (lane < NTHREADS / 32) ? s_red[lane] : 0.0f;
        #pragma unroll
        for (int off = 4; off > 0; off >>= 1)
            acc += __shfl_down_sync(0xFFFFFFFFu, acc, off);
        if (lane == 0) {
            g_partials[blockIdx.x] = acc;
            __threadfence();
            unsigned int tk = atomicAdd(&g_ticket, 1u);
            s_is_last = (tk == (unsigned int)(GRID - 1));
        }
    }
    __syncthreads();

    if (!s_is_last) return;

    // Last block: fixed-order reduce of GRID partials (deterministic).
    const volatile float* vp = (const volatile float*)g_partials;
    float tacc = 0.0f;
    for (int jj = tid; jj < GRID; jj += NTHREADS)
        tacc += vp[jj];

    #pragma unroll
    for (int off = 16; off > 0; off >>= 1)
        tacc += __shfl_down_sync(0xFFFFFFFFu, tacc, off);

    if (lane == 0) s_red[warp] = tacc;
    __syncthreads();

    if (warp == 0) {
        tacc = (lane < NTHREADS / 32) ? s_red[lane] : 0.0f;
        #pragma unroll
        for (int off = 4; off > 0; off >>= 1)
            tacc += __shfl_down_sync(0xFFFFFFFFu, tacc, off);
        if (lane == 0) {
            out[0] = tacc * scale;
            g_ticket = 0;           // reset for graph replay
            __threadfence();
        }
    }
}

extern "C" void kernel_launch(void* const* d_in, const int* in_sizes, int n_in,
                              void* d_out, int out_size)
{
    const float* p_mu = (const float*)d_in[0];
    const float* p_lv = (const float*)d_in[1];
    const float* q_mu = (const float*)d_in[2];
    const float* q_lv = (const float*)d_in[3];
    float* out = (float*)d_out;

    int n = in_sizes[0];               // B*D = 8388608
    int n_tiles = n / TILE_FLOATS;     // 8192
    int B = n / 512;                   // D = 512
    float scale = 0.5f / (float)B;

    kl_bulk_kernel<<<GRID, NTHREADS>>>(p_mu, p_lv, q_mu, q_lv, out, n_tiles, scale);
}

// round 8
// speedup vs baseline: 1.1735x; 1.1735x over previous
#include <cuda_runtime.h>
#include <cuda_bf16.h>

// KL(p||q) for diagonal Gaussians, mean over batch.
// Two kernels (Round-1 structure: best measured main-loop codegen, ~6.5 TB/s)
// + PDL: the finish kernel is launched with programmatic stream serialization
// and opens with cudaGridDependencySynchronize(), so its launch latency
// overlaps the primary kernel's execution instead of serializing after it.
// Deterministic: fixed grid, fixed reduction order, no float atomics.

#define NBLOCKS 1024
#define NTHREADS 256

__device__ float g_partials[NBLOCKS];

__global__ __launch_bounds__(NTHREADS) void kl_partial_kernel(
    const float* __restrict__ p_mu,
    const float* __restrict__ p_lv,
    const float* __restrict__ q_mu,
    const float* __restrict__ q_lv,
    int n4)
{
    // Let the dependent (finish) kernel launch immediately; it will block in
    // cudaGridDependencySynchronize() until this grid completes.
    cudaTriggerProgrammaticLaunchCompletion();

    const float4* pm4 = reinterpret_cast<const float4*>(p_mu);
    const float4* pl4 = reinterpret_cast<const float4*>(p_lv);
    const float4* qm4 = reinterpret_cast<const float4*>(q_mu);
    const float4* ql4 = reinterpret_cast<const float4*>(q_lv);

    float acc = 0.0f;
    int stride = gridDim.x * blockDim.x;
    for (int i = blockIdx.x * blockDim.x + threadIdx.x; i < n4; i += stride) {
        float4 a = pm4[i];
        float4 b = pl4[i];
        float4 c = qm4[i];
        float4 d = ql4[i];

        {
            float lr = d.x - b.x;
            float dm = a.x - c.x;
            acc += lr + __expf(-lr) + dm * dm * __expf(-d.x) - 1.0f;
        }
        {
            float lr = d.y - b.y;
            float dm = a.y - c.y;
            acc += lr + __expf(-lr) + dm * dm * __expf(-d.y) - 1.0f;
        }
        {
            float lr = d.z - b.z;
            float dm = a.z - c.z;
            acc += lr + __expf(-lr) + dm * dm * __expf(-d.z) - 1.0f;
        }
        {
            float lr = d.w - b.w;
            float dm = a.w - c.w;
            acc += lr + __expf(-lr) + dm * dm * __expf(-d.w) - 1.0f;
        }
    }

    // warp reduce
    #pragma unroll
    for (int off = 16; off > 0; off >>= 1)
        acc += __shfl_down_sync(0xFFFFFFFFu, acc, off);

    __shared__ float smem[NTHREADS / 32];
    int lane = threadIdx.x & 31;
    int warp = threadIdx.x >> 5;
    if (lane == 0) smem[warp] = acc;
    __syncthreads();

    if (warp == 0) {
        acc = (lane < NTHREADS / 32) ? smem[lane] : 0.0f;
        #pragma unroll
        for (int off = 4; off > 0; off >>= 1)
            acc += __shfl_down_sync(0xFFFFFFFFu, acc, off);
        if (lane == 0) g_partials[blockIdx.x] = acc;
    }
}

__global__ __launch_bounds__(1024) void kl_finish_kernel(float* out, float scale)
{
    // Launched early via PDL; wait here until the primary grid (and all its
    // memory writes) completes.
    cudaGridDependencySynchronize();

    float acc = g_partials[threadIdx.x];

    #pragma unroll
    for (int off = 16; off > 0; off >>= 1)
        acc += __shfl_down_sync(0xFFFFFFFFu, acc, off);

    __shared__ float smem[32];
    int lane = threadIdx.x & 31;
    int warp = threadIdx.x >> 5;
    if (lane == 0) smem[warp] = acc;
    __syncthreads();

    if (warp == 0) {
        acc = smem[lane];
        #pragma unroll
        for (int off = 16; off > 0; off >>= 1)
            acc += __shfl_down_sync(0xFFFFFFFFu, acc, off);
        if (lane == 0) out[0] = acc * scale;
    }
}

extern "C" void kernel_launch(void* const* d_in, const int* in_sizes, int n_in,
                              void* d_out, int out_size)
{
    const float* p_mu = (const float*)d_in[0];
    const float* p_lv = (const float*)d_in[1];
    const float* q_mu = (const float*)d_in[2];
    const float* q_lv = (const float*)d_in[3];
    float* out = (float*)d_out;

    int n  = in_sizes[0];     // B*D
    int n4 = n >> 2;
    int B  = n / 512;         // D = 512
    float scale = 0.5f / (float)B;

    kl_partial_kernel<<<NBLOCKS, NTHREADS>>>(p_mu, p_lv, q_mu, q_lv, n4);

    // Finish kernel with programmatic dependent launch: overlaps its launch
    // latency with the primary kernel's execution.
    cudaLaunchConfig_t cfg = {};
    cfg.gridDim  = dim3(1, 1, 1);
    cfg.blockDim = dim3(1024, 1, 1);
    cfg.dynamicSmemBytes = 0;
    cfg.stream = 0;
    cudaLaunchAttribute attrs[1];
    attrs[0].id = cudaLaunchAttributeProgrammaticStreamSerialization;
    attrs[0].val.programmaticStreamSerializationAllowed = 1;
    cfg.attrs = attrs;
    cfg.numAttrs = 1;
    cudaLaunchKernelEx(&cfg, kl_finish_kernel, out, scale);
}